// round 1
// baseline (speedup 1.0000x reference)
#include <cuda_runtime.h>
#include <cstdint>
#include <cfloat>

// YOLOPredict: decode 98 boxes/item, per-class (20) greedy NMS, write [bs,20,98,6].
// One warp per batch item; suppression (iou>0.5) precomputed as 98x128-bit masks.

namespace {

constexpr int S_    = 7;
constexpr int NC_   = 20;
constexpr int NCELL = 49;          // S*S
constexpr int NBOX  = 98;          // S*S*B
constexpr int CHAN  = 30;          // B*5 + NC
constexpr int WPB   = 4;           // warps (= items) per block

struct __align__(16) ItemSmem {
    float4   xyxy[NBOX];           // decoded, clipped boxes
    uint32_t sup[NBOX * 4];        // row r: 128-bit mask of (iou(r,j) > 0.5)
    float    pred[NCELL * CHAN];   // raw input for this item
};

__global__ __launch_bounds__(WPB * 32)
void yolo_nms_kernel(const float* __restrict__ g_pred,
                     float* __restrict__ g_out, int batch)
{
    __shared__ ItemSmem sm[WPB];
    const int lane = threadIdx.x & 31;
    const int wid  = threadIdx.x >> 5;
    const int item = blockIdx.x * WPB + wid;
    if (item >= batch) return;
    ItemSmem& s = sm[wid];

    // ---- Phase 0: coalesced load of this item's 49x30 floats ----
    const float* gp = g_pred + (size_t)item * (NCELL * CHAN);
    for (int t = lane; t < NCELL * CHAN; t += 32)
        s.pred[t] = __ldg(&gp[t]);
    __syncwarp();

    // ---- Phase 1: decode boxes. Lane owns boxes n = lane + 32k, k=0..3 ----
    float bx1[4], by1[4], bx2[4], by2[4], barea[4], bconf[4];
    int cbase[4];
    const float cellf = 1.0f / 7.0f;
#pragma unroll
    for (int k = 0; k < 4; k++) {
        int n  = lane + 32 * k;
        int nn = n < NBOX ? n : NBOX - 1;      // clamp for safe (unused) reads
        int cell = nn >> 1;
        int bb   = nn & 1;
        int ci = cell / S_, cj = cell % S_;    // ci = first spatial index (x uses it)
        const float* p = &s.pred[cell * CHAN + bb * 5];
        float cx = (p[0] + (float)ci) * cellf;
        float cy = (p[1] + (float)cj) * cellf;
        float hw = p[2] * 0.5f;
        float hh = p[3] * 0.5f;
        float x1 = fminf(fmaxf(cx - hw, 0.0f), 1.0f);
        float y1 = fminf(fmaxf(cy - hh, 0.0f), 1.0f);
        float x2 = fminf(fmaxf(cx + hw, 0.0f), 1.0f);
        float y2 = fminf(fmaxf(cy + hh, 0.0f), 1.0f);
        bx1[k] = x1; by1[k] = y1; bx2[k] = x2; by2[k] = y2;
        barea[k] = (x2 - x1) * (y2 - y1);
        bconf[k] = p[4];
        cbase[k] = cell * CHAN + 10;           // class-conf base for this box's cell
        if (n < NBOX) s.xyxy[n] = make_float4(x1, y1, x2, y2);
    }
    __syncwarp();

    // ---- Phase 2: suppression bitmasks. Row r = lane+32k vs all columns j ----
    // IEEE division (__fdiv_rn) so iou>0.5 decisions match the reference bitwise.
#pragma unroll
    for (int w = 0; w < 4; w++) {
        uint32_t acc[4] = {0u, 0u, 0u, 0u};
        const int jcnt = (w == 3) ? (NBOX - 96) : 32;
        for (int jj = 0; jj < jcnt; jj++) {
            float4 bj = s.xyxy[w * 32 + jj];           // uniform -> broadcast LDS
            float  aj = (bj.z - bj.x) * (bj.w - bj.y); // recompute area (3 flops < LDS)
#pragma unroll
            for (int k = 0; k < 4; k++) {
                float iw = fmaxf(fminf(bx2[k], bj.z) - fmaxf(bx1[k], bj.x), 0.0f);
                float ih = fmaxf(fminf(by2[k], bj.w) - fmaxf(by1[k], bj.y), 0.0f);
                float inter = iw * ih;
                float denom = (barea[k] + aj) - inter;
                float iou   = __fdiv_rn(inter, denom);
                acc[k] |= (iou > 0.5f ? 1u : 0u) << jj;
            }
        }
#pragma unroll
        for (int k = 0; k < 4; k++) {
            int n = lane + 32 * k;
            if (n < NBOX) s.sup[n * 4 + w] = acc[k];
        }
    }
    __syncwarp();

    // ---- Phase 3: per-class greedy NMS (== reference's rank-ordered fori_loop) ----
    for (int c = 0; c < NC_; c++) {
        float sc[4];
        uint32_t cand = 0u, keepb = 0u;
#pragma unroll
        for (int k = 0; k < 4; k++) {
            sc[k] = s.pred[cbase[k] + c] * bconf[k];
            int n = lane + 32 * k;
            if (n < NBOX && sc[k] > 0.1f) cand |= 1u << k;
        }

        while (__ballot_sync(0xffffffffu, cand != 0u)) {
            // warp argmax over candidates; ties -> smallest index (stable argsort)
            float bestv = -FLT_MAX;
            int   besti = 0x7fffffff;
#pragma unroll
            for (int k = 0; k < 4; k++) {
                if ((cand >> k) & 1u) {
                    if (sc[k] > bestv) { bestv = sc[k]; besti = lane + 32 * k; }
                }
            }
#pragma unroll
            for (int off = 16; off > 0; off >>= 1) {
                float ov = __shfl_xor_sync(0xffffffffu, bestv, off);
                int   oi = __shfl_xor_sync(0xffffffffu, besti, off);
                if (ov > bestv || (ov == bestv && oi < besti)) { bestv = ov; besti = oi; }
            }
            // keep the winner; remove it from candidacy (also guards NaN self-iou)
            if (lane == (besti & 31)) {
                keepb |= 1u << (besti >> 5);
                cand  &= ~(1u << (besti >> 5));
            }
            // suppress overlapping candidates (all have strictly lower rank)
            const uint4 m = *reinterpret_cast<const uint4*>(&s.sup[besti * 4]);
            uint32_t supb =  ((m.x >> lane) & 1u)
                          | (((m.y >> lane) & 1u) << 1)
                          | (((m.z >> lane) & 1u) << 2)
                          | (((m.w >> lane) & 1u) << 3);
            cand &= ~supb;
        }

        // ---- write [item, c, n, 0..5] = {xyxy*kf, score*kf, kf} ----
        float* ob = g_out + ((size_t)item * NC_ + c) * (NBOX * 6);
#pragma unroll
        for (int k = 0; k < 4; k++) {
            int n = lane + 32 * k;
            if (n < NBOX) {
                float mk = ((keepb >> k) & 1u) ? 1.0f : 0.0f;
                float* o = ob + n * 6;                       // 24B stride, 8B aligned
                *reinterpret_cast<float2*>(o)     = make_float2(bx1[k] * mk, by1[k] * mk);
                *reinterpret_cast<float2*>(o + 2) = make_float2(bx2[k] * mk, by2[k] * mk);
                *reinterpret_cast<float2*>(o + 4) = make_float2(sc[k]  * mk, mk);
            }
        }
    }
}

} // namespace

extern "C" void kernel_launch(void* const* d_in, const int* in_sizes, int n_in,
                              void* d_out, int out_size) {
    const float* pred = (const float*)d_in[0];
    float* out = (float*)d_out;
    const int batch = in_sizes[0] / (NCELL * CHAN);
    const int grid  = (batch + WPB - 1) / WPB;
    yolo_nms_kernel<<<grid, WPB * 32>>>(pred, out, batch);
}

// round 14
// speedup vs baseline: 2.4892x; 2.4892x over previous
#include <cuda_runtime.h>
#include <cstdint>

// YOLOPredict: decode 98 boxes/item, per-class (20) greedy NMS, write [bs,20,98,6].
// TWO warps per item (block = item): phase2 IoU columns and phase3 classes are
// split across the warps. NMS argmax via packed-key REDUX; suppression via
// transposed nibble masks (1 LDS.U8 per round). Exact reference semantics
// (__fdiv_rn IoU, stable smallest-index tie-break).

namespace {

constexpr int S_    = 7;
constexpr int NC_   = 20;
constexpr int NCELL = 49;          // S*S
constexpr int NBOX  = 98;          // S*S*B
constexpr int CHAN  = 30;          // B*5 + NC
constexpr int NTHR  = 64;          // 2 warps = 1 item

struct __align__(16) ItemSmem {
    float4  xyxy[NBOX];            // decoded, clipped boxes           1568 B
    float   pred[NCELL * CHAN];    // raw input for this item          5880 B
    uint8_t nib[NBOX * 32];        // nib[j*32+lane] bit k: row (lane+32k) suppressed by col j
};                                 //                                  3136 B  (10584 total)

__global__ __launch_bounds__(NTHR)
void yolo_nms_kernel(const float* __restrict__ g_pred,
                     float* __restrict__ g_out)
{
    __shared__ ItemSmem s;
    const int tid  = threadIdx.x;
    const int lane = tid & 31;
    const int warp = tid >> 5;
    const int item = blockIdx.x;

    // ---- Phase 0: coalesced load of this item's 49x30 floats (64 threads) ----
    const float* gp = g_pred + (size_t)item * (NCELL * CHAN);
    for (int t = tid; t < NCELL * CHAN; t += NTHR)
        s.pred[t] = __ldg(&gp[t]);
    __syncthreads();

    // ---- Phase 1: decode. Thread t decodes boxes n = t, t+64 ----
    const float cellf = 1.0f / 7.0f;
#pragma unroll
    for (int r = 0; r < 2; r++) {
        int n = tid + NTHR * r;
        if (n < NBOX) {
            int cell = n >> 1, bb = n & 1;
            int ci = cell / S_, cj = cell % S_;    // ci = first spatial index (x uses it)
            const float* p = &s.pred[cell * CHAN + bb * 5];
            float cx = (p[0] + (float)ci) * cellf;
            float cy = (p[1] + (float)cj) * cellf;
            float hw = p[2] * 0.5f;
            float hh = p[3] * 0.5f;
            float x1 = fminf(fmaxf(cx - hw, 0.0f), 1.0f);
            float y1 = fminf(fmaxf(cy - hh, 0.0f), 1.0f);
            float x2 = fminf(fmaxf(cx + hw, 0.0f), 1.0f);
            float y2 = fminf(fmaxf(cy + hh, 0.0f), 1.0f);
            s.xyxy[n] = make_float4(x1, y1, x2, y2);
        }
    }
    __syncthreads();

    // ---- Per-warp row registers: rows n = lane + 32k, k = 0..3 ----
    float bx1[4], by1[4], bx2[4], by2[4], barea[4], bconf[4];
    int cbase[4];
#pragma unroll
    for (int k = 0; k < 4; k++) {
        int n  = lane + 32 * k;
        int nn = n < NBOX ? n : NBOX - 1;          // clamp for safe (unused) reads
        float4 b = s.xyxy[nn];
        bx1[k] = b.x; by1[k] = b.y; bx2[k] = b.z; by2[k] = b.w;
        barea[k] = (b.z - b.x) * (b.w - b.y);
        int cell = nn >> 1, bb = nn & 1;
        bconf[k] = s.pred[cell * CHAN + bb * 5 + 4];
        cbase[k] = cell * CHAN + 10;               // class-conf base for this row's cell
    }

    // ---- Phase 2: suppression nibbles; warp w builds columns [49w, 49w+49).
    // Self bit forced (handles zero-area 0/0 NaN). IEEE division so iou>0.5
    // decisions match the reference bitwise.
    for (int jj = 0; jj < NCELL; jj++) {
        int j = warp * NCELL + jj;
        float4 bj = s.xyxy[j];                     // warp-uniform -> broadcast LDS
        float  aj = (bj.z - bj.x) * (bj.w - bj.y);
        unsigned nb = 0u;
#pragma unroll
        for (int k = 0; k < 4; k++) {
            float iw = fmaxf(fminf(bx2[k], bj.z) - fmaxf(bx1[k], bj.x), 0.0f);
            float ih = fmaxf(fminf(by2[k], bj.w) - fmaxf(by1[k], bj.y), 0.0f);
            float inter = iw * ih;
            float denom = (barea[k] + aj) - inter;
            float iou   = __fdiv_rn(inter, denom);
            unsigned bit = (iou > 0.5f) || ((lane + 32 * k) == j);
            nb |= bit << k;
        }
        s.nib[j * 32 + lane] = (uint8_t)nb;
    }
    __syncthreads();

    // ---- Phase 3: warp w runs greedy NMS for classes [10w, 10w+10).
    // key = ((bits(sc) - bits(0.1f)) << 7) | (127 - n): order-preserving for
    // sc in (0.1, 1), ties broken by smallest n (== stable argsort of reference).
    const unsigned BITS01 = 0x3DCCCCCDu;           // __float_as_uint(0.1f)
    for (int cc = 0; cc < NC_ / 2; cc++) {
        int c = warp * (NC_ / 2) + cc;
        float sc[4];
        unsigned key[4];
        unsigned keepb = 0u;
#pragma unroll
        for (int k = 0; k < 4; k++) {
            int n = lane + 32 * k;
            sc[k] = s.pred[cbase[k] + c] * bconf[k];
            unsigned b  = __float_as_uint(sc[k]);
            unsigned pk = ((b - BITS01) << 7) | (unsigned)(127 - n);
            key[k] = (n < NBOX && sc[k] > 0.1f) ? pk : 0u;
        }

        while (true) {
            unsigned v0 = key[0] > key[1] ? key[0] : key[1];
            unsigned v1 = key[2] > key[3] ? key[2] : key[3];
            unsigned wbest = __reduce_max_sync(0xffffffffu, v0 > v1 ? v0 : v1);
            if (wbest == 0u) break;
            int besti = 127 - (int)(wbest & 127u);
            unsigned nb = (unsigned)s.nib[besti * 32 + lane];
            if (lane == (besti & 31)) keepb |= 1u << (besti >> 5);
            // clear suppressed candidates (incl. the winner via its self bit)
#pragma unroll
            for (int k = 0; k < 4; k++)
                if ((nb >> k) & 1u) key[k] = 0u;
        }

        // ---- write [item, c, n, 0..5] = {xyxy*kf, score*kf, kf} ----
        float* ob = g_out + ((size_t)item * NC_ + c) * (NBOX * 6);
#pragma unroll
        for (int k = 0; k < 4; k++) {
            int n = lane + 32 * k;
            if (n < NBOX) {
                float mk = ((keepb >> k) & 1u) ? 1.0f : 0.0f;
                float* o = ob + n * 6;                       // 24B stride, 8B aligned
                *reinterpret_cast<float2*>(o)     = make_float2(bx1[k] * mk, by1[k] * mk);
                *reinterpret_cast<float2*>(o + 2) = make_float2(bx2[k] * mk, by2[k] * mk);
                *reinterpret_cast<float2*>(o + 4) = make_float2(sc[k]  * mk, mk);
            }
        }
    }
}

} // namespace

extern "C" void kernel_launch(void* const* d_in, const int* in_sizes, int n_in,
                              void* d_out, int out_size) {
    const float* pred = (const float*)d_in[0];
    float* out = (float*)d_out;
    const int batch = in_sizes[0] / (NCELL * CHAN);
    yolo_nms_kernel<<<batch, NTHR>>>(pred, out);
}